// round 9
// baseline (speedup 1.0000x reference)
#include <cuda_runtime.h>
#include <cuda_bf16.h>

// IDW interpolation, POWER=2:  w = 1/d^2 (sqrt cancels).
//
// Round 9: 4 independent point-pack chains per thread (8 points). R7/R8
// evidence: neither issue (65-69%) nor fma pipe (59%) saturates at occ
// 54-67% -- latency-bound on LDS->d2->prod->MUFU(16cyc)->accum chains.
// More warps didn't help (R7); more ILP did (R8). So: max ILP, spend
// registers. 3 LDS.128 + loop overhead now amortized over 4x math.
//
// Pairing identity for d2 values a,b (1 rcp per 2 stations per point):
//   w1+w2       = (a+b)/(a*b)
//   w1*v1+w2*v2 = (v1*b + v2*a)/(a*b)
// d==0: fold +1e-12 into d^2 (dominating weight -> same ratio; no branch;
// pair product can't underflow).

#define NSTATIONS 512
#define SPLITS 8
#define PAIRS_PER_SPLIT 32             // 64 stations per split-warp
#define CHAINS 4                       // point-packs per thread (8 points)
#define PACKS_PER_BLOCK 128            // 32 lanes * 4 chains
#define TPB 256                        // 8 warps: split = warp id
#define NPACKS 131072                  // total points / 2

typedef unsigned long long u64;

__device__ __forceinline__ u64 f2_pack(float lo, float hi) {
    u64 r; asm("mov.b64 %0, {%1, %2};" : "=l"(r) : "f"(lo), "f"(hi)); return r;
}
__device__ __forceinline__ void f2_unpack(u64 a, float& lo, float& hi) {
    asm("mov.b64 {%0, %1}, %2;" : "=f"(lo), "=f"(hi) : "l"(a));
}
__device__ __forceinline__ u64 f2_add(u64 a, u64 b) {
    u64 r; asm("add.rn.f32x2 %0, %1, %2;" : "=l"(r) : "l"(a), "l"(b)); return r;
}
__device__ __forceinline__ u64 f2_mul(u64 a, u64 b) {
    u64 r; asm("mul.rn.f32x2 %0, %1, %2;" : "=l"(r) : "l"(a), "l"(b)); return r;
}
__device__ __forceinline__ u64 f2_fma(u64 a, u64 b, u64 c) {
    u64 r; asm("fma.rn.f32x2 %0, %1, %2, %3;" : "=l"(r) : "l"(a), "l"(b), "l"(c)); return r;
}
__device__ __forceinline__ float frcp(float a) {
    float r; asm("rcp.approx.f32 %0, %1;" : "=f"(r) : "f"(a)); return r;
}
__device__ __forceinline__ u64 f2_rcp(u64 a) {
    float lo, hi; f2_unpack(a, lo, hi);
    return f2_pack(frcp(lo), frcp(hi));
}

__global__ __launch_bounds__(TPB) void idw_fused(
    const float* __restrict__ station_coords,  // (B, S, 2)
    const float* __restrict__ station_values,  // (B, S)
    const float* __restrict__ grid_points,     // (B, P, 2)
    float* __restrict__ out,                   // (B, P) flat
    int P)
{
    // 256 station pairs, 6 u64 each (3 x 16B -> LDS.128 broadcast):
    //  [0]=(-x1,-x1) [1]=(-y1,-y1) [2]=(-x2,-x2) [3]=(-y2,-y2) [4]=(v1,v1) [5]=(v2,v2)
    __shared__ u64 sh[(NSTATIONS / 2) * 6];           // 12 KB
    __shared__ float4 red[SPLITS * PACKS_PER_BLOCK];  // 16 KB partials

    const int tid   = threadIdx.x;
    const int split = tid >> 5;                    // warp id, 0..7
    const int lane  = tid & 31;
    const int packbase = blockIdx.x * PACKS_PER_BLOCK;
    const int b = (packbase * 2) / P;  // 256 points/block divides P: one batch

    // Stage: one station pair per thread (LDG.128 + LDG.64 -> 3x STS.128)
    {
        const float4 c = reinterpret_cast<const float4*>(
            station_coords + (size_t)b * NSTATIONS * 2)[tid];
        const float2 v = reinterpret_cast<const float2*>(
            station_values + (size_t)b * NSTATIONS)[tid];
        ulonglong2* dst = reinterpret_cast<ulonglong2*>(sh + tid * 6);
        dst[0] = make_ulonglong2(f2_pack(-c.x, -c.x), f2_pack(-c.y, -c.y));
        dst[1] = make_ulonglong2(f2_pack(-c.z, -c.z), f2_pack(-c.w, -c.w));
        dst[2] = make_ulonglong2(f2_pack(v.x, v.x),   f2_pack(v.y, v.y));
    }
    __syncthreads();

    // 4 packs per thread: chain q owns pack (lane + 32*q). Coalesced float4.
    u64 gx[CHAINS], gy[CHAINS], ws[CHAINS], vs[CHAINS];
    #pragma unroll
    for (int q = 0; q < CHAINS; q++) {
        const float4 a = reinterpret_cast<const float4*>(
            grid_points)[packbase + 32 * q + lane];
        gx[q] = f2_pack(a.x, a.z);
        gy[q] = f2_pack(a.y, a.w);
        ws[q] = 0ull;
        vs[q] = 0ull;
    }

    const u64 eps2 = f2_pack(1e-12f, 1e-12f);
    const ulonglong2* sh2 = reinterpret_cast<const ulonglong2*>(sh)
                          + (size_t)split * PAIRS_PER_SPLIT * 3;

    #pragma unroll 2
    for (int p = 0; p < PAIRS_PER_SPLIT; p++) {
        const ulonglong2 c1 = sh2[p * 3 + 0];  // (nx1, ny1)  LDS.128 broadcast
        const ulonglong2 c2 = sh2[p * 3 + 1];  // (nx2, ny2)
        const ulonglong2 vv = sh2[p * 3 + 2];  // (vv1, vv2)

        #pragma unroll
        for (int q = 0; q < CHAINS; q++) {     // 4 independent chains
            u64 dx1 = f2_add(gx[q], c1.x);
            u64 dy1 = f2_add(gy[q], c1.y);
            u64 da  = f2_fma(dy1, dy1, eps2);
            da      = f2_fma(dx1, dx1, da);        // a = d2 of station 1
            u64 dx2 = f2_add(gx[q], c2.x);
            u64 dy2 = f2_add(gy[q], c2.y);
            u64 db  = f2_fma(dy2, dy2, eps2);
            db      = f2_fma(dx2, dx2, db);        // b = d2 of station 2
            u64 sum  = f2_add(da, db);             // a + b
            u64 prod = f2_mul(da, db);             // a * b
            u64 num  = f2_mul(vv.x, db);
            num      = f2_fma(vv.y, da, num);      // v1*b + v2*a
            u64 r    = f2_rcp(prod);               // 2x MUFU.RCP per 2 stations
            ws[q] = f2_fma(sum, r, ws[q]);
            vs[q] = f2_fma(num, r, vs[q]);
        }
    }

    // Partials -> smem
    #pragma unroll
    for (int q = 0; q < CHAINS; q++) {
        float w0, w1, n0, n1;
        f2_unpack(ws[q], w0, w1);
        f2_unpack(vs[q], n0, n1);
        red[split * PACKS_PER_BLOCK + 32 * q + lane] = make_float4(w0, w1, n0, n1);
    }
    __syncthreads();

    // Threads 0..127 reduce 8 splits for one pack each (fixed order, det.)
    if (tid < PACKS_PER_BLOCK) {
        float4 acc = red[tid];
        #pragma unroll
        for (int k = 1; k < SPLITS; k++) {
            float4 t = red[k * PACKS_PER_BLOCK + tid];  // conflict-free LDS.128
            acc.x += t.x; acc.y += t.y; acc.z += t.z; acc.w += t.w;
        }
        float2 r;
        r.x = acc.z * frcp(acc.x);
        r.y = acc.w * frcp(acc.y);
        reinterpret_cast<float2*>(out)[packbase + tid] = r;
    }
}

extern "C" void kernel_launch(void* const* d_in, const int* in_sizes, int n_in,
                              void* d_out, int out_size) {
    const float* station_coords = (const float*)d_in[0];  // (B,S,2)
    const float* station_values = (const float*)d_in[1];  // (B,S)
    const float* grid_points    = (const float*)d_in[2];  // (B,P,2)
    float* out = (float*)d_out;

    const int S = NSTATIONS;                 // 512 per problem spec
    const int B = in_sizes[1] / S;           // 2
    const int P = in_sizes[2] / (B * 2);     // 131072

    const int blocks = NPACKS / PACKS_PER_BLOCK;  // 1024 blocks, 8192 warps
    idw_fused<<<blocks, TPB>>>(station_coords, station_values, grid_points,
                               out, P);
}

// round 10
// speedup vs baseline: 1.0061x; 1.0061x over previous
#include <cuda_runtime.h>
#include <cuda_bf16.h>

// IDW interpolation, POWER=2:  w = 1/d^2 (sqrt cancels).
//
// Round 10: SOFTWARE-PIPELINED RCP. R7-R9 evidence: fma pinned ~59%,
// issue 63-69% across occ 33-67% and ILP 1-4 -- latency-bound on the
// prod -> unpack -> MUFU.RCP(16cyc) -> pack -> accum tail; extra chains
// don't help because ptxas shares temps across chains (regs=71 at ILP-4).
// Fix: defer each pair's rcp+accumulate by one loop iteration. Iteration p
// issues rcp(prod[p-1]) first, computes body p (14 independent FP ops that
// fill the MUFU shadow), then accumulates pair p-1. Only +3 u64 saved
// state per chain. Shape = R8 (2 chains, 8 split-warps, 16384 warps).
//
// Pairing identity for d2 values a,b (1 rcp per 2 stations per point):
//   w1+w2       = (a+b)/(a*b)
//   w1*v1+w2*v2 = (v1*b + v2*a)/(a*b)
// d==0: fold +1e-12 into d^2 (dominating weight -> same ratio; no branch;
// pair product can't underflow).

#define NSTATIONS 512
#define SPLITS 8
#define PAIRS_PER_SPLIT 32             // 64 stations per split-warp
#define PACKS_PER_BLOCK 64             // 128 grid points per block
#define TPB 256                        // 8 warps: split = warp id
#define NPACKS 131072                  // total points / 2

typedef unsigned long long u64;

__device__ __forceinline__ u64 f2_pack(float lo, float hi) {
    u64 r; asm("mov.b64 %0, {%1, %2};" : "=l"(r) : "f"(lo), "f"(hi)); return r;
}
__device__ __forceinline__ void f2_unpack(u64 a, float& lo, float& hi) {
    asm("mov.b64 {%0, %1}, %2;" : "=f"(lo), "=f"(hi) : "l"(a));
}
__device__ __forceinline__ u64 f2_add(u64 a, u64 b) {
    u64 r; asm("add.rn.f32x2 %0, %1, %2;" : "=l"(r) : "l"(a), "l"(b)); return r;
}
__device__ __forceinline__ u64 f2_mul(u64 a, u64 b) {
    u64 r; asm("mul.rn.f32x2 %0, %1, %2;" : "=l"(r) : "l"(a), "l"(b)); return r;
}
__device__ __forceinline__ u64 f2_fma(u64 a, u64 b, u64 c) {
    u64 r; asm("fma.rn.f32x2 %0, %1, %2, %3;" : "=l"(r) : "l"(a), "l"(b), "l"(c)); return r;
}
__device__ __forceinline__ float frcp(float a) {
    float r; asm("rcp.approx.f32 %0, %1;" : "=f"(r) : "f"(a)); return r;
}
__device__ __forceinline__ u64 f2_rcp(u64 a) {
    float lo, hi; f2_unpack(a, lo, hi);
    return f2_pack(frcp(lo), frcp(hi));
}

struct PairState { u64 sum, num, prod; };

// Compute one pair-body for one point-pack; returns sum/num/prod (no rcp).
__device__ __forceinline__ PairState pair_body(
    u64 gx, u64 gy, ulonglong2 c1, ulonglong2 c2, ulonglong2 vv, u64 eps2)
{
    u64 dx1 = f2_add(gx, c1.x);
    u64 dy1 = f2_add(gy, c1.y);
    u64 da  = f2_fma(dy1, dy1, eps2);
    da      = f2_fma(dx1, dx1, da);        // a = d2 of station 1
    u64 dx2 = f2_add(gx, c2.x);
    u64 dy2 = f2_add(gy, c2.y);
    u64 db  = f2_fma(dy2, dy2, eps2);
    db      = f2_fma(dx2, dx2, db);        // b = d2 of station 2
    PairState s;
    s.sum  = f2_add(da, db);               // a + b
    s.prod = f2_mul(da, db);               // a * b
    s.num  = f2_mul(vv.x, db);
    s.num  = f2_fma(vv.y, da, s.num);      // v1*b + v2*a
    return s;
}

__global__ __launch_bounds__(TPB) void idw_fused(
    const float* __restrict__ station_coords,  // (B, S, 2)
    const float* __restrict__ station_values,  // (B, S)
    const float* __restrict__ grid_points,     // (B, P, 2)
    float* __restrict__ out,                   // (B, P) flat
    int P)
{
    // 256 station pairs, 6 u64 each (3 x 16B -> LDS.128 broadcast):
    //  [0]=(-x1,-x1) [1]=(-y1,-y1) [2]=(-x2,-x2) [3]=(-y2,-y2) [4]=(v1,v1) [5]=(v2,v2)
    __shared__ u64 sh[(NSTATIONS / 2) * 6];           // 12 KB
    __shared__ float4 red[SPLITS * PACKS_PER_BLOCK];  // 8 KB partials

    const int tid   = threadIdx.x;
    const int split = tid >> 5;                    // warp id, 0..7
    const int lane  = tid & 31;
    const int packbase = blockIdx.x * PACKS_PER_BLOCK;
    const int b = (packbase * 2) / P;  // 128 points/block divides P: one batch

    // Stage: one station pair per thread (LDG.128 + LDG.64 -> 3x STS.128)
    {
        const float4 c = reinterpret_cast<const float4*>(
            station_coords + (size_t)b * NSTATIONS * 2)[tid];
        const float2 v = reinterpret_cast<const float2*>(
            station_values + (size_t)b * NSTATIONS)[tid];
        ulonglong2* dst = reinterpret_cast<ulonglong2*>(sh + tid * 6);
        dst[0] = make_ulonglong2(f2_pack(-c.x, -c.x), f2_pack(-c.y, -c.y));
        dst[1] = make_ulonglong2(f2_pack(-c.z, -c.z), f2_pack(-c.w, -c.w));
        dst[2] = make_ulonglong2(f2_pack(v.x, v.x),   f2_pack(v.y, v.y));
    }
    __syncthreads();

    // Two packs per thread (chains 0/1), coalesced float4 loads.
    const float4 a0 = reinterpret_cast<const float4*>(grid_points)[packbase + lane];
    const float4 a1 = reinterpret_cast<const float4*>(grid_points)[packbase + 32 + lane];
    const u64 gx0 = f2_pack(a0.x, a0.z), gy0 = f2_pack(a0.y, a0.w);
    const u64 gx1 = f2_pack(a1.x, a1.z), gy1 = f2_pack(a1.y, a1.w);

    const u64 eps2 = f2_pack(1e-12f, 1e-12f);
    u64 ws0 = 0ull, vs0 = 0ull, ws1 = 0ull, vs1 = 0ull;

    const ulonglong2* sh2 = reinterpret_cast<const ulonglong2*>(sh)
                          + (size_t)split * PAIRS_PER_SPLIT * 3;

    // ── Software pipeline: prologue computes pair 0; iteration p issues
    //    rcp(prod[p-1]) before computing body p, accumulates p-1 after.
    PairState s0, s1;
    {
        const ulonglong2 c1 = sh2[0], c2 = sh2[1], vv = sh2[2];
        s0 = pair_body(gx0, gy0, c1, c2, vv, eps2);
        s1 = pair_body(gx1, gy1, c1, c2, vv, eps2);
    }

    #pragma unroll 4
    for (int p = 1; p < PAIRS_PER_SPLIT; p++) {
        // Issue both rcps first: 4 MUFU in flight over the body compute.
        u64 r0 = f2_rcp(s0.prod);
        u64 r1 = f2_rcp(s1.prod);

        const ulonglong2 c1 = sh2[p * 3 + 0];  // LDS.128 broadcast
        const ulonglong2 c2 = sh2[p * 3 + 1];
        const ulonglong2 vv = sh2[p * 3 + 2];
        PairState t0 = pair_body(gx0, gy0, c1, c2, vv, eps2);
        PairState t1 = pair_body(gx1, gy1, c1, c2, vv, eps2);

        // Accumulate previous pair (r now long ready).
        ws0 = f2_fma(s0.sum, r0, ws0);
        vs0 = f2_fma(s0.num, r0, vs0);
        ws1 = f2_fma(s1.sum, r1, ws1);
        vs1 = f2_fma(s1.num, r1, vs1);

        s0 = t0;
        s1 = t1;
    }
    {   // Epilogue: last pair.
        u64 r0 = f2_rcp(s0.prod);
        u64 r1 = f2_rcp(s1.prod);
        ws0 = f2_fma(s0.sum, r0, ws0);
        vs0 = f2_fma(s0.num, r0, vs0);
        ws1 = f2_fma(s1.sum, r1, ws1);
        vs1 = f2_fma(s1.num, r1, vs1);
    }

    // Partials -> smem
    {
        float w0, w1, n0, n1;
        f2_unpack(ws0, w0, w1);  f2_unpack(vs0, n0, n1);
        red[split * PACKS_PER_BLOCK + lane] = make_float4(w0, w1, n0, n1);
        f2_unpack(ws1, w0, w1);  f2_unpack(vs1, n0, n1);
        red[split * PACKS_PER_BLOCK + 32 + lane] = make_float4(w0, w1, n0, n1);
    }
    __syncthreads();

    // Threads 0..63 reduce 8 splits for one pack each (fixed order, det.)
    if (tid < PACKS_PER_BLOCK) {
        float4 acc = red[tid];
        #pragma unroll
        for (int k = 1; k < SPLITS; k++) {
            float4 t = red[k * PACKS_PER_BLOCK + tid];  // conflict-free LDS.128
            acc.x += t.x; acc.y += t.y; acc.z += t.z; acc.w += t.w;
        }
        float2 r;
        r.x = acc.z * frcp(acc.x);
        r.y = acc.w * frcp(acc.y);
        reinterpret_cast<float2*>(out)[packbase + tid] = r;
    }
}

extern "C" void kernel_launch(void* const* d_in, const int* in_sizes, int n_in,
                              void* d_out, int out_size) {
    const float* station_coords = (const float*)d_in[0];  // (B,S,2)
    const float* station_values = (const float*)d_in[1];  // (B,S)
    const float* grid_points    = (const float*)d_in[2];  // (B,P,2)
    float* out = (float*)d_out;

    const int S = NSTATIONS;                 // 512 per problem spec
    const int B = in_sizes[1] / S;           // 2
    const int P = in_sizes[2] / (B * 2);     // 131072

    const int blocks = NPACKS / PACKS_PER_BLOCK;  // 2048 blocks, 16384 warps
    idw_fused<<<blocks, TPB>>>(station_coords, station_values, grid_points,
                               out, P);
}